// round 16
// baseline (speedup 1.0000x reference)
#include <cuda_runtime.h>
#include <cuda_fp16.h>
#include <cstdint>

#define NN   50000   // nodes
#define KNB  16      // neighbors
#define D    256     // feature dim
#define NC   50      // classes
#define NB   4096    // batch
#define NEG_SLOPE 0.2f

// -------- scratch (static device allocations; no cudaMalloc allowed) --------
__device__ __half g_hw_h[NN * D];   // h @ W (fp16, gather array)
__device__ __half g_h16[NN * D];    // layer output (fp16)
__device__ __half g_a16[NN * D];    // node_feat pre-converted to fp16
__device__ __half g_w16[2 * D * D]; // fp16 copies of both layer weights ([k][n])
__device__ float  g_src[2 * NN];
__device__ float  g_dst[2 * NN];
__device__ int    g_idx64;

__device__ __forceinline__ int load_idx(const void* p, long long i) {
    if (g_idx64) return (int)((const long long*)p)[i];
    return ((const int*)p)[i];
}

__device__ __forceinline__ float warp_red_sum(float v) {
#pragma unroll
    for (int o = 16; o > 0; o >>= 1) v += __shfl_xor_sync(0xffffffffu, v, o);
    return v;
}

#define CP_ASYNC16Z(dst_u32, src, nbytes) \
    asm volatile("cp.async.cg.shared.global [%0], [%1], 16, %2;" \
                 :: "r"(dst_u32), "l"(src), "r"(nbytes))
#define CP_ASYNC16(dst_u32, src) \
    asm volatile("cp.async.cg.shared.global [%0], [%1], 16;" :: "r"(dst_u32), "l"(src))
#define CP_COMMIT() asm volatile("cp.async.commit_group;")
#define CP_WAIT1()  asm volatile("cp.async.wait_group 1;")
#define CP_WAIT0()  asm volatile("cp.async.wait_group 0;")

// ---------------------------------------------------------------------------
// init: zero src/dst, convert W + node_feat -> fp16, detect idx dtype.
// ---------------------------------------------------------------------------
__global__ void init_kernel(const float* __restrict__ Ws,
                            const float* __restrict__ node_feat,
                            const int* __restrict__ nb, int n_words) {
    int i = blockIdx.x * blockDim.x + threadIdx.x;
    if (i < 2 * NN) { g_src[i] = 0.f; g_dst[i] = 0.f; }
    if (i < 2 * D * D / 4) {
        float4 f = ((const float4*)Ws)[i];
        __half2 h01 = __floats2half2_rn(f.x, f.y);
        __half2 h23 = __floats2half2_rn(f.z, f.w);
        ((uint2*)g_w16)[i] = make_uint2(*(uint32_t*)&h01, *(uint32_t*)&h23);
    }
    if (i < NN * D / 4) {
        float4 f = ((const float4*)node_feat)[i];
        __half2 h01 = __floats2half2_rn(f.x, f.y);
        __half2 h23 = __floats2half2_rn(f.z, f.w);
        ((uint2*)g_a16)[i] = make_uint2(*(uint32_t*)&h01, *(uint32_t*)&h23);
    }
    if (blockIdx.x == 0) {
        int bad = 0;
        for (int j = 1 + 2 * threadIdx.x; j < n_words; j += 2 * blockDim.x)
            if (nb[j] != 0) bad = 1;
        int any = __syncthreads_or(bad);
        if (threadIdx.x == 0) g_idx64 = any ? 0 : 1;
    }
}

// ---------------------------------------------------------------------------
// fp16 mma.sync GEMM, 512 threads / 16 warps, warptile 32x32, 64 regs,
// 2 CTAs/SM. Block tile 128x128x32, THREE-stage cp.async ring (depth-2
// prefetch) in dynamic smem; wait_group 1 per tile hides load latency.
// A smem [m][k] pad-40 (conflict-free ldmatrix.x4).
// B smem [k][n] BSTR=128, chunk XOR swizzle (nch ^ (krow&15)).
// Fused epilogue: src/dst dots (smem-combined, then global atomics) + fp16 hw.
// ---------------------------------------------------------------------------
#define GBM 128
#define GBN 128
#define GBK 32
#define ASTR 40
#define BSTRH 128
#define A_STG (GBM * ASTR)    // 5120 halves / stage
#define B_STG (GBK * BSTRH)   // 4096 halves / stage
#define NKB  (D / GBK)        // 8
#define GEMM_DSMEM ((3 * A_STG + 3 * B_STG) * 2)   // 55296 bytes

template <int LAYER>
__global__ void __launch_bounds__(512, 2) tc_gemm_kernel(
    const float* __restrict__ a_s, const float* __restrict__ a_d)
{
    extern __shared__ __half smem_dyn[];
    __half* Abase = smem_dyn;                // 3 stages of A
    __half* Bbase = smem_dyn + 3 * A_STG;    // 3 stages of B
    __shared__ float ssrc[GBM], sdst[GBM];

    float* srcp = g_src + LAYER * NN;
    float* dstp = g_dst + LAYER * NN;
    const __half* Wl  = g_w16 + LAYER * D * D;
    const __half* A16 = LAYER ? g_h16 : g_a16;

    const int tid    = threadIdx.x;
    const int wid    = tid >> 5;
    const int lane   = tid & 31;
    const int groupr = lane >> 2;
    const int qk     = lane & 3;
    const int warpM  = wid & 3;       // 0..3  (32 rows each)
    const int warpN  = wid >> 2;      // 0..3  (32 cols each)
    const int m0     = blockIdx.y * GBM;
    const int n0     = blockIdx.x * GBN;

    if (tid < GBM) { ssrc[tid] = 0.f; sdst[tid] = 0.f; }

    float c[2][4][4];
#pragma unroll
    for (int mt = 0; mt < 2; mt++)
#pragma unroll
        for (int nt = 0; nt < 4; nt++)
#pragma unroll
            for (int j = 0; j < 4; j++) c[mt][nt][j] = 0.f;

    // A chunk mapping: row mr = tid>>2, chunk hc = tid&3 (8 halves each)
    const int a_mr = tid >> 2;
    const int a_hc = tid & 3;
    // B chunk mapping: krow = tid>>4 (0..31), nch = tid&15
    const int b_kr = tid >> 4;
    const int b_nc = tid & 15;

    auto issue_AB = [&](int kt, int stg) {
        int kb = kt * GBK;
        int m  = m0 + a_mr;
        const __half* asrc = A16 + (size_t)m * D + kb + a_hc * 8;
        uint32_t adst = (uint32_t)__cvta_generic_to_shared(
            &Abase[stg * A_STG + a_mr * ASTR + a_hc * 8]);
        CP_ASYNC16Z(adst, asrc, (m < NN) ? 16 : 0);
        const __half* bsrc = Wl + (size_t)(kb + b_kr) * D + n0 + b_nc * 8;
        uint32_t bdst = (uint32_t)__cvta_generic_to_shared(
            &Bbase[stg * B_STG + b_kr * BSTRH + ((b_nc ^ (b_kr & 15)) << 3)]);
        CP_ASYNC16(bdst, bsrc);
        CP_COMMIT();
    };

    issue_AB(0, 0);
    issue_AB(1, 1);

    int stg = 0;     // stage of current compute tile
    for (int kbi = 0; kbi < NKB; kbi++) {
        if (kbi == NKB - 1) CP_WAIT0(); else CP_WAIT1();
        __syncthreads();
        if (kbi + 2 < NKB) {
            int nstg = stg - 1; if (nstg < 0) nstg = 2;   // (kbi+2)%3
            issue_AB(kbi + 2, nstg);
        }

        const __half* Ab = Abase + stg * A_STG;
        const __half* Bb = Bbase + stg * B_STG;
#pragma unroll
        for (int ks = 0; ks < 2; ks++) {
            uint32_t af[2][4];
#pragma unroll
            for (int mt = 0; mt < 2; mt++) {
                int row = warpM * 32 + mt * 16 + (lane & 15);
                int col = ks * 16 + ((lane >> 4) << 3);
                uint32_t addr =
                    (uint32_t)__cvta_generic_to_shared(&Ab[row * ASTR + col]);
                asm volatile(
                    "ldmatrix.sync.aligned.m8n8.x4.shared.b16 {%0,%1,%2,%3}, [%4];"
                    : "=r"(af[mt][0]), "=r"(af[mt][1]),
                      "=r"(af[mt][2]), "=r"(af[mt][3]) : "r"(addr));
            }
#pragma unroll
            for (int np = 0; np < 2; np++) {
                int krow = ks * 16 + (lane & 15);
                int nc   = warpN * 4 + np * 2 + ((lane & 16) ? 1 : 0);
                uint32_t baddr = (uint32_t)__cvta_generic_to_shared(
                    &Bb[krow * BSTRH + ((nc ^ (krow & 15)) << 3)]);
                uint32_t b0, b1, b2, b3;
                asm volatile(
                    "ldmatrix.sync.aligned.m8n8.x4.trans.shared.b16 {%0,%1,%2,%3}, [%4];"
                    : "=r"(b0), "=r"(b1), "=r"(b2), "=r"(b3) : "r"(baddr));
#pragma unroll
                for (int mt = 0; mt < 2; mt++) {
                    asm volatile(
                        "mma.sync.aligned.m16n8k16.row.col.f32.f16.f16.f32 "
                        "{%0,%1,%2,%3}, {%4,%5,%6,%7}, {%8,%9}, {%0,%1,%2,%3};"
                        : "+f"(c[mt][2*np][0]), "+f"(c[mt][2*np][1]),
                          "+f"(c[mt][2*np][2]), "+f"(c[mt][2*np][3])
                        : "r"(af[mt][0]), "r"(af[mt][1]),
                          "r"(af[mt][2]), "r"(af[mt][3]),
                          "r"(b0), "r"(b1));
                    asm volatile(
                        "mma.sync.aligned.m16n8k16.row.col.f32.f16.f16.f32 "
                        "{%0,%1,%2,%3}, {%4,%5,%6,%7}, {%8,%9}, {%0,%1,%2,%3};"
                        : "+f"(c[mt][2*np+1][0]), "+f"(c[mt][2*np+1][1]),
                          "+f"(c[mt][2*np+1][2]), "+f"(c[mt][2*np+1][3])
                        : "r"(af[mt][0]), "r"(af[mt][1]),
                          "r"(af[mt][2]), "r"(af[mt][3]),
                          "r"(b2), "r"(b3));
                }
            }
        }
        stg++; if (stg == 3) stg = 0;
    }

    // ---- epilogue: hw store (fp16) + src/dst dots via smem combine ----
    float sp[2][2] = {{0.f, 0.f}, {0.f, 0.f}};
    float dp[2][2] = {{0.f, 0.f}, {0.f, 0.f}};
#pragma unroll
    for (int mt = 0; mt < 2; mt++) {
        int rlo = m0 + warpM * 32 + mt * 16 + groupr;
        int rhi = rlo + 8;
#pragma unroll
        for (int nt = 0; nt < 4; nt++) {
            int col = n0 + warpN * 32 + nt * 8 + 2 * qk;
            float as0 = __ldg(a_s + col), as1 = __ldg(a_s + col + 1);
            float ad0 = __ldg(a_d + col), ad1 = __ldg(a_d + col + 1);
            float v0 = c[mt][nt][0], v1 = c[mt][nt][1];
            float v2 = c[mt][nt][2], v3 = c[mt][nt][3];
            sp[mt][0] += v0 * as0 + v1 * as1;
            dp[mt][0] += v0 * ad0 + v1 * ad1;
            sp[mt][1] += v2 * as0 + v3 * as1;
            dp[mt][1] += v2 * ad0 + v3 * ad1;
            if (rlo < NN)
                *(__half2*)(g_hw_h + (size_t)rlo * D + col) = __floats2half2_rn(v0, v1);
            if (rhi < NN)
                *(__half2*)(g_hw_h + (size_t)rhi * D + col) = __floats2half2_rn(v2, v3);
        }
    }
#pragma unroll
    for (int mt = 0; mt < 2; mt++)
#pragma unroll
        for (int hf = 0; hf < 2; hf++) {
            float s = sp[mt][hf], d = dp[mt][hf];
            s += __shfl_xor_sync(0xffffffffu, s, 1);
            s += __shfl_xor_sync(0xffffffffu, s, 2);
            d += __shfl_xor_sync(0xffffffffu, d, 1);
            d += __shfl_xor_sync(0xffffffffu, d, 2);
            if (qk == 0) {
                int rl = warpM * 32 + mt * 16 + groupr + hf * 8;
                atomicAdd(&ssrc[rl], s);   // block-scope smem combine
                atomicAdd(&sdst[rl], d);
            }
        }
    __syncthreads();
    if (tid < GBM) {
        int m = m0 + tid;
        if (m < NN) {
            atomicAdd(&srcp[m], ssrc[tid]);   // across the 2 column blocks
            atomicAdd(&dstp[m], sdst[tid]);
        }
    }
}

// ---------------------------------------------------------------------------
// Attention + aggregation + ELU. One warp per node; fp16 gather + fp16 out.
// ---------------------------------------------------------------------------
__global__ void agg_kernel(const void* __restrict__ neighbors, int layer) {
    int w    = (blockIdx.x * blockDim.x + threadIdx.x) >> 5;
    int lane = threadIdx.x & 31;
    if (w >= NN) return;
    const float* srcp = g_src + layer * NN;
    const float* dstp = g_dst + layer * NN;

    int   nbr = 0;
    float e   = -1e30f;
    if (lane < KNB) {
        nbr = load_idx(neighbors, (long long)w * KNB + lane);
        e   = srcp[w] + dstp[nbr];
        e   = e > 0.f ? e : NEG_SLOPE * e;
    }
    float m = e;
#pragma unroll
    for (int o = 8; o > 0; o >>= 1) m = fmaxf(m, __shfl_xor_sync(0xffffffffu, m, o));
    float ex = (lane < KNB) ? __expf(e - m) : 0.f;
    float s = ex;
#pragma unroll
    for (int o = 8; o > 0; o >>= 1) s += __shfl_xor_sync(0xffffffffu, s, o);
    float alpha = ex / s;

    float acc[8] = {0.f, 0.f, 0.f, 0.f, 0.f, 0.f, 0.f, 0.f};
#pragma unroll
    for (int k = 0; k < KNB; k++) {
        float al  = __shfl_sync(0xffffffffu, alpha, k);
        int   idx = __shfl_sync(0xffffffffu, nbr, k);
        uint4 v = *((const uint4*)(g_hw_h + (size_t)idx * D) + lane);
        const __half2* hp = (const __half2*)&v;
        float2 f0 = __half22float2(hp[0]);
        float2 f1 = __half22float2(hp[1]);
        float2 f2 = __half22float2(hp[2]);
        float2 f3 = __half22float2(hp[3]);
        acc[0] += al * f0.x; acc[1] += al * f0.y;
        acc[2] += al * f1.x; acc[3] += al * f1.y;
        acc[4] += al * f2.x; acc[5] += al * f2.y;
        acc[6] += al * f3.x; acc[7] += al * f3.y;
    }
#pragma unroll
    for (int j = 0; j < 8; j++)
        acc[j] = acc[j] > 0.f ? acc[j] : __expf(acc[j]) - 1.f;

    uint4 ov;
    __half2* op = (__half2*)&ov;
    op[0] = __floats2half2_rn(acc[0], acc[1]);
    op[1] = __floats2half2_rn(acc[2], acc[3]);
    op[2] = __floats2half2_rn(acc[4], acc[5]);
    op[3] = __floats2half2_rn(acc[6], acc[7]);
    *((uint4*)(g_h16 + (size_t)w * D) + lane) = ov;
}

// ---------------------------------------------------------------------------
// Classification head.
// ---------------------------------------------------------------------------
__global__ void cls_kernel(const void* __restrict__ node,
                           const float* __restrict__ cls_W,
                           const float* __restrict__ cls_b,
                           float* __restrict__ out) {
    int b    = (blockIdx.x * blockDim.x + threadIdx.x) >> 5;
    int lane = threadIdx.x & 31;
    if (b >= NB) return;
    int n = load_idx(node, b);
    uint4 v = *((const uint4*)(g_h16 + (size_t)n * D) + lane);
    const __half2* hp = (const __half2*)&v;
    float2 f0 = __half22float2(hp[0]);
    float2 f1 = __half22float2(hp[1]);
    float2 f2 = __half22float2(hp[2]);
    float2 f3 = __half22float2(hp[3]);
    for (int c = 0; c < NC; c++) {
        const float4* wr = (const float4*)(cls_W + (size_t)c * D);
        float4 w0 = wr[lane * 2], w1 = wr[lane * 2 + 1];
        float p = f0.x * w0.x + f0.y * w0.y + f1.x * w0.z + f1.y * w0.w
                + f2.x * w1.x + f2.y * w1.y + f3.x * w1.z + f3.y * w1.w;
        p = warp_red_sum(p);
        if (lane == 0) out[(size_t)b * NC + c] = p + cls_b[c];
    }
}

// ---------------------------------------------------------------------------
extern "C" void kernel_launch(void* const* d_in, const int* in_sizes, int n_in,
                              void* d_out, int out_size) {
    const void*  node      = d_in[0];
    const float* node_feat = (const float*)d_in[1];
    const void*  neighbors = d_in[2];
    const float* Ws        = (const float*)d_in[3];
    const float* a_src     = (const float*)d_in[4];
    const float* a_dst     = (const float*)d_in[5];
    const float* cls_W     = (const float*)d_in[6];
    const float* cls_b     = (const float*)d_in[7];
    float* out = (float*)d_out;

    const int warp_blocks = (NN * 32 + 255) / 256;  // 6250

    cudaFuncSetAttribute(tc_gemm_kernel<0>,
        cudaFuncAttributeMaxDynamicSharedMemorySize, GEMM_DSMEM);
    cudaFuncSetAttribute(tc_gemm_kernel<1>,
        cudaFuncAttributeMaxDynamicSharedMemorySize, GEMM_DSMEM);

    int n_words = in_sizes[2] < 2048 ? in_sizes[2] : 2048;
    init_kernel<<<(NN * D / 4 + 255) / 256, 256>>>(Ws, node_feat,
                                                   (const int*)neighbors, n_words);

    dim3 ggrid(D / GBN, (NN + GBM - 1) / GBM);      // (2, 391)
    tc_gemm_kernel<0><<<ggrid, 512, GEMM_DSMEM>>>(a_src, a_dst);
    agg_kernel<<<warp_blocks, 256>>>(neighbors, 0);
    tc_gemm_kernel<1><<<ggrid, 512, GEMM_DSMEM>>>(a_src + D, a_dst + D);
    agg_kernel<<<warp_blocks, 256>>>(neighbors, 1);
    cls_kernel<<<(NB * 32 + 255) / 256, 256>>>(node, cls_W, cls_b, out);
}

// round 17
// speedup vs baseline: 1.0595x; 1.0595x over previous
#include <cuda_runtime.h>
#include <cuda_fp16.h>
#include <cstdint>

#define NN   50000   // nodes
#define KNB  16      // neighbors
#define D    256     // feature dim
#define NC   50      // classes
#define NB   4096    // batch
#define NEG_SLOPE 0.2f

// -------- scratch (static device allocations; no cudaMalloc allowed) --------
__device__ __half g_hw_h[NN * D];   // h @ W (fp16, gather array)
__device__ __half g_h16[NN * D];    // layer output (fp16)
__device__ __half g_w16[2 * D * D]; // fp16 copies of both layer weights ([k][n])
__device__ float  g_src[2 * NN];
__device__ float  g_dst[2 * NN];
__device__ int    g_idx64;

__device__ __forceinline__ int load_idx(const void* p, long long i) {
    if (g_idx64) return (int)((const long long*)p)[i];
    return ((const int*)p)[i];
}

__device__ __forceinline__ float warp_red_sum(float v) {
#pragma unroll
    for (int o = 16; o > 0; o >>= 1) v += __shfl_xor_sync(0xffffffffu, v, o);
    return v;
}

#define CP_ASYNC16Z(dst_u32, src, nbytes) \
    asm volatile("cp.async.cg.shared.global [%0], [%1], 16, %2;" \
                 :: "r"(dst_u32), "l"(src), "r"(nbytes))
#define CP_ASYNC16(dst_u32, src) \
    asm volatile("cp.async.cg.shared.global [%0], [%1], 16;" :: "r"(dst_u32), "l"(src))
#define CP_COMMIT() asm volatile("cp.async.commit_group;")
#define CP_WAIT1()  asm volatile("cp.async.wait_group 1;")
#define CP_WAIT0()  asm volatile("cp.async.wait_group 0;")

// ---------------------------------------------------------------------------
// init: zero src/dst, convert W -> fp16 ([k][n]), detect idx dtype.
// (No node_feat conversion — layer 0 stages fp32 A in registers.)
// ---------------------------------------------------------------------------
__global__ void init_kernel(const float* __restrict__ Ws,
                            const int* __restrict__ nb, int n_words) {
    int i = blockIdx.x * blockDim.x + threadIdx.x;
    if (i < 2 * NN) { g_src[i] = 0.f; g_dst[i] = 0.f; }
    if (i < 2 * D * D / 4) {
        float4 f = ((const float4*)Ws)[i];
        __half2 h01 = __floats2half2_rn(f.x, f.y);
        __half2 h23 = __floats2half2_rn(f.z, f.w);
        ((uint2*)g_w16)[i] = make_uint2(*(uint32_t*)&h01, *(uint32_t*)&h23);
    }
    if (blockIdx.x == 0) {
        int bad = 0;
        for (int j = 1 + 2 * threadIdx.x; j < n_words; j += 2 * blockDim.x)
            if (nb[j] != 0) bad = 1;
        int any = __syncthreads_or(bad);
        if (threadIdx.x == 0) g_idx64 = any ? 0 : 1;
    }
}

// ===========================================================================
// GEMM LAYER 0 — measured-best R8 configuration: 256 threads / 8 warps,
// warptile 32x64, A register-staged fp32 node_feat -> fp16 (1 ahead, As[2]),
// B cp.async 3-stage from g_w16 (2 ahead, Bs[3], pad-136).
// Fused epilogue: src/dst dots via shuffle + direct global atomics.
// ===========================================================================
#define GBM 128
#define GBN 128
#define GBK 32
#define ASTR 40
#define BSTR 136
#define NKB  (D / GBK)   // 8

__global__ void __launch_bounds__(256) gemm0_kernel(
    const float* __restrict__ Aext,
    const float* __restrict__ a_s, const float* __restrict__ a_d)
{
    float* srcp = g_src;
    float* dstp = g_dst;
    const __half* Wl = g_w16;

    __shared__ __half As[2][GBM * ASTR];
    __shared__ __half Bs[3][GBK * BSTR];

    const int tid    = threadIdx.x;
    const int wid    = tid >> 5;
    const int lane   = tid & 31;
    const int groupr = lane >> 2;
    const int qk     = lane & 3;
    const int warpM  = wid >> 1;
    const int warpN  = wid & 1;
    const int m0     = blockIdx.y * GBM;
    const int n0     = blockIdx.x * GBN;

    float c[2][8][4];
#pragma unroll
    for (int mt = 0; mt < 2; mt++)
#pragma unroll
        for (int nt = 0; nt < 8; nt++)
#pragma unroll
            for (int j = 0; j < 4; j++) c[mt][nt][j] = 0.f;

    const int a_mr = tid >> 3;        // 0..31
    const int a_k4 = (tid & 7) * 4;   // 0..28

    float4 fa[4];

    auto issue_B = [&](int kt) {
#pragma unroll
        for (int rep = 0; rep < 2; rep++) {
            int cch  = tid + rep * 256;
            int krow = cch >> 4;
            int nch  = cch & 15;
            const __half* src = Wl + (size_t)(kt * GBK + krow) * D + n0 + nch * 8;
            uint32_t dst = (uint32_t)__cvta_generic_to_shared(
                &Bs[kt % 3][krow * BSTR + nch * 8]);
            CP_ASYNC16(dst, src);
        }
        CP_COMMIT();
    };
    auto load_A = [&](int kt) {
        int kb = kt * GBK;
#pragma unroll
        for (int it = 0; it < 4; it++) {
            int m = m0 + a_mr + it * 32;
            fa[it] = make_float4(0.f, 0.f, 0.f, 0.f);
            if (m < NN) fa[it] = *(const float4*)(Aext + (size_t)m * D + kb + a_k4);
        }
    };
    auto sts_A = [&](int kt) {
        __half* buf = As[kt & 1];
#pragma unroll
        for (int it = 0; it < 4; it++) {
            int mr = a_mr + it * 32;
            __half2 a01 = __floats2half2_rn(fa[it].x, fa[it].y);
            __half2 a23 = __floats2half2_rn(fa[it].z, fa[it].w);
            *(uint2*)&buf[mr * ASTR + a_k4] =
                make_uint2(*(uint32_t*)&a01, *(uint32_t*)&a23);
        }
    };

    // ---- prologue ----
    load_A(0); sts_A(0); load_A(1);
    issue_B(0);
    issue_B(1);

    for (int kbi = 0; kbi < NKB; kbi++) {
        if (kbi == NKB - 1) CP_WAIT0(); else CP_WAIT1();
        __syncthreads();
        if (kbi + 2 < NKB) issue_B(kbi + 2);
        if (kbi + 1 < NKB) sts_A(kbi + 1);
        if (kbi + 2 < NKB) load_A(kbi + 2);

        const __half* Ab = As[kbi & 1];
        const __half* Bb = Bs[kbi % 3];
#pragma unroll
        for (int ks = 0; ks < 2; ks++) {
            uint32_t af[2][4];
#pragma unroll
            for (int mt = 0; mt < 2; mt++) {
                int row = warpM * 32 + mt * 16 + (lane & 15);
                int col = ks * 16 + ((lane >> 4) << 3);
                uint32_t addr =
                    (uint32_t)__cvta_generic_to_shared(&Ab[row * ASTR + col]);
                asm volatile(
                    "ldmatrix.sync.aligned.m8n8.x4.shared.b16 {%0,%1,%2,%3}, [%4];"
                    : "=r"(af[mt][0]), "=r"(af[mt][1]),
                      "=r"(af[mt][2]), "=r"(af[mt][3]) : "r"(addr));
            }
#pragma unroll
            for (int np = 0; np < 4; np++) {
                int krow = ks * 16 + (lane & 15);
                int ncol = warpN * 64 + np * 16 + ((lane & 16) ? 8 : 0);
                uint32_t baddr =
                    (uint32_t)__cvta_generic_to_shared(&Bb[krow * BSTR + ncol]);
                uint32_t b0, b1, b2, b3;
                asm volatile(
                    "ldmatrix.sync.aligned.m8n8.x4.trans.shared.b16 {%0,%1,%2,%3}, [%4];"
                    : "=r"(b0), "=r"(b1), "=r"(b2), "=r"(b3) : "r"(baddr));
#pragma unroll
                for (int mt = 0; mt < 2; mt++) {
                    asm volatile(
                        "mma.sync.aligned.m16n8k16.row.col.f32.f16.f16.f32 "
                        "{%0,%1,%2,%3}, {%4,%5,%6,%7}, {%8,%9}, {%0,%1,%2,%3};"
                        : "+f"(c[mt][2*np][0]), "+f"(c[mt][2*np][1]),
                          "+f"(c[mt][2*np][2]), "+f"(c[mt][2*np][3])
                        : "r"(af[mt][0]), "r"(af[mt][1]),
                          "r"(af[mt][2]), "r"(af[mt][3]),
                          "r"(b0), "r"(b1));
                    asm volatile(
                        "mma.sync.aligned.m16n8k16.row.col.f32.f16.f16.f32 "
                        "{%0,%1,%2,%3}, {%4,%5,%6,%7}, {%8,%9}, {%0,%1,%2,%3};"
                        : "+f"(c[mt][2*np+1][0]), "+f"(c[mt][2*np+1][1]),
                          "+f"(c[mt][2*np+1][2]), "+f"(c[mt][2*np+1][3])
                        : "r"(af[mt][0]), "r"(af[mt][1]),
                          "r"(af[mt][2]), "r"(af[mt][3]),
                          "r"(b2), "r"(b3));
                }
            }
        }
    }

    // ---- epilogue: store hw (fp16) + fused src/dst dots + direct atomics ----
    float sp[2][2] = {{0.f, 0.f}, {0.f, 0.f}};
    float dp[2][2] = {{0.f, 0.f}, {0.f, 0.f}};
#pragma unroll
    for (int mt = 0; mt < 2; mt++) {
        int rlo = m0 + warpM * 32 + mt * 16 + groupr;
        int rhi = rlo + 8;
#pragma unroll
        for (int nt = 0; nt < 8; nt++) {
            int col = n0 + warpN * 64 + nt * 8 + 2 * qk;
            float as0 = __ldg(a_s + col), as1 = __ldg(a_s + col + 1);
            float ad0 = __ldg(a_d + col), ad1 = __ldg(a_d + col + 1);
            float v0 = c[mt][nt][0], v1 = c[mt][nt][1];
            float v2 = c[mt][nt][2], v3 = c[mt][nt][3];
            sp[mt][0] += v0 * as0 + v1 * as1;
            dp[mt][0] += v0 * ad0 + v1 * ad1;
            sp[mt][1] += v2 * as0 + v3 * as1;
            dp[mt][1] += v2 * ad0 + v3 * ad1;
            if (rlo < NN)
                *(__half2*)(g_hw_h + (size_t)rlo * D + col) = __floats2half2_rn(v0, v1);
            if (rhi < NN)
                *(__half2*)(g_hw_h + (size_t)rhi * D + col) = __floats2half2_rn(v2, v3);
        }
    }
#pragma unroll
    for (int mt = 0; mt < 2; mt++)
#pragma unroll
        for (int hf = 0; hf < 2; hf++) {
            float s = sp[mt][hf], d = dp[mt][hf];
            s += __shfl_xor_sync(0xffffffffu, s, 1);
            s += __shfl_xor_sync(0xffffffffu, s, 2);
            d += __shfl_xor_sync(0xffffffffu, d, 1);
            d += __shfl_xor_sync(0xffffffffu, d, 2);
            if (qk == 0) {
                int r = m0 + warpM * 32 + mt * 16 + groupr + hf * 8;
                if (r < NN) {
                    atomicAdd(&srcp[r], s);
                    atomicAdd(&dstp[r], d);
                }
            }
        }
}

// ===========================================================================
// GEMM LAYER 1 — measured-best R15 configuration: 512 threads / 16 warps,
// warptile 32x32 (64 regs, 2 CTAs/SM), pure cp.async A (fp16 g_h16) + B,
// double-buffered. Epilogue: smem-combined src/dst + global atomics.
// ===========================================================================
#define BSTRH 128
#define A_STG (GBM * ASTR)    // 5120 halves
#define B_STG (GBK * BSTRH)   // 4096 halves

__global__ void __launch_bounds__(512, 2) gemm1_kernel(
    const float* __restrict__ a_s, const float* __restrict__ a_d)
{
    __shared__ __half As[2][A_STG];
    __shared__ __half Bs[2][B_STG];
    __shared__ float  ssrc[GBM], sdst[GBM];

    float* srcp = g_src + NN;
    float* dstp = g_dst + NN;
    const __half* Wl  = g_w16 + D * D;
    const __half* A16 = g_h16;

    const int tid    = threadIdx.x;
    const int wid    = tid >> 5;
    const int lane   = tid & 31;
    const int groupr = lane >> 2;
    const int qk     = lane & 3;
    const int warpM  = wid & 3;
    const int warpN  = wid >> 2;
    const int m0     = blockIdx.y * GBM;
    const int n0     = blockIdx.x * GBN;

    if (tid < GBM) { ssrc[tid] = 0.f; sdst[tid] = 0.f; }

    float c[2][4][4];
#pragma unroll
    for (int mt = 0; mt < 2; mt++)
#pragma unroll
        for (int nt = 0; nt < 4; nt++)
#pragma unroll
            for (int j = 0; j < 4; j++) c[mt][nt][j] = 0.f;

    const int a_mr = tid >> 2;
    const int a_hc = tid & 3;
    const int b_kr = tid >> 4;
    const int b_nc = tid & 15;

    auto issue_AB = [&](int kt) {
        int kb = kt * GBK;
        int m  = m0 + a_mr;
        const __half* asrc = A16 + (size_t)m * D + kb + a_hc * 8;
        uint32_t adst = (uint32_t)__cvta_generic_to_shared(
            &As[kt & 1][a_mr * ASTR + a_hc * 8]);
        CP_ASYNC16Z(adst, asrc, (m < NN) ? 16 : 0);
        const __half* bsrc = Wl + (size_t)(kb + b_kr) * D + n0 + b_nc * 8;
        uint32_t bdst = (uint32_t)__cvta_generic_to_shared(
            &Bs[kt & 1][b_kr * BSTRH + ((b_nc ^ (b_kr & 15)) << 3)]);
        CP_ASYNC16(bdst, bsrc);
        CP_COMMIT();
    };

    issue_AB(0);

    for (int kbi = 0; kbi < NKB; kbi++) {
        CP_WAIT0();
        __syncthreads();
        if (kbi + 1 < NKB) issue_AB(kbi + 1);

        const __half* Ab = As[kbi & 1];
        const __half* Bb = Bs[kbi & 1];
#pragma unroll
        for (int ks = 0; ks < 2; ks++) {
            uint32_t af[2][4];
#pragma unroll
            for (int mt = 0; mt < 2; mt++) {
                int row = warpM * 32 + mt * 16 + (lane & 15);
                int col = ks * 16 + ((lane >> 4) << 3);
                uint32_t addr =
                    (uint32_t)__cvta_generic_to_shared(&Ab[row * ASTR + col]);
                asm volatile(
                    "ldmatrix.sync.aligned.m8n8.x4.shared.b16 {%0,%1,%2,%3}, [%4];"
                    : "=r"(af[mt][0]), "=r"(af[mt][1]),
                      "=r"(af[mt][2]), "=r"(af[mt][3]) : "r"(addr));
            }
#pragma unroll
            for (int np = 0; np < 2; np++) {
                int krow = ks * 16 + (lane & 15);
                int nc   = warpN * 4 + np * 2 + ((lane & 16) ? 1 : 0);
                uint32_t baddr = (uint32_t)__cvta_generic_to_shared(
                    &Bb[krow * BSTRH + ((nc ^ (krow & 15)) << 3)]);
                uint32_t b0, b1, b2, b3;
                asm volatile(
                    "ldmatrix.sync.aligned.m8n8.x4.trans.shared.b16 {%0,%1,%2,%3}, [%4];"
                    : "=r"(b0), "=r"(b1), "=r"(b2), "=r"(b3) : "r"(baddr));
#pragma unroll
                for (int mt = 0; mt < 2; mt++) {
                    asm volatile(
                        "mma.sync.aligned.m16n8k16.row.col.f32.f16.f16.f32 "
                        "{%0,%1,%2,%3}, {%4,%5,%6,%7}, {%8,%9}, {%0,%1,%2,%3};"
                        : "+f"(c[mt][2*np][0]), "+f"(c[mt][2*np][1]),
                          "+f"(c[mt][2*np][2]), "+f"(c[mt][2*np][3])
                        : "r"(af[mt][0]), "r"(af[mt][1]),
                          "r"(af[mt][2]), "r"(af[mt][3]),
                          "r"(b0), "r"(b1));
                    asm volatile(
                        "mma.sync.aligned.m16n8k16.row.col.f32.f16.f16.f32 "
                        "{%0,%1,%2,%3}, {%4,%5,%6,%7}, {%8,%9}, {%0,%1,%2,%3};"
                        : "+f"(c[mt][2*np+1][0]), "+f"(c[mt][2*np+1][1]),
                          "+f"(c[mt][2*np+1][2]), "+f"(c[mt][2*np+1][3])
                        : "r"(af[mt][0]), "r"(af[mt][1]),
                          "r"(af[mt][2]), "r"(af[mt][3]),
                          "r"(b2), "r"(b3));
                }
            }
        }
    }

    // ---- epilogue ----
    float sp[2][2] = {{0.f, 0.f}, {0.f, 0.f}};
    float dp[2][2] = {{0.f, 0.f}, {0.f, 0.f}};
#pragma unroll
    for (int mt = 0; mt < 2; mt++) {
        int rlo = m0 + warpM * 32 + mt * 16 + groupr;
        int rhi = rlo + 8;
#pragma unroll
        for (int nt = 0; nt < 4; nt++) {
            int col = n0 + warpN * 32 + nt * 8 + 2 * qk;
            float as0 = __ldg(a_s + col), as1 = __ldg(a_s + col + 1);
            float ad0 = __ldg(a_d + col), ad1 = __ldg(a_d + col + 1);
            float v0 = c[mt][nt][0], v1 = c[mt][nt][1];
            float v2 = c[mt][nt][2], v3 = c[mt][nt][3];
            sp[mt][0] += v0 * as0 + v1 * as1;
            dp[mt][0] += v0 * ad0 + v1 * ad1;
            sp[mt][1] += v2 * as0 + v3 * as1;
            dp[mt][1] += v2 * ad0 + v3 * ad1;
            if (rlo < NN)
                *(__half2*)(g_hw_h + (size_t)rlo * D + col) = __floats2half2_rn(v0, v1);
            if (rhi < NN)
                *(__half2*)(g_hw_h + (size_t)rhi * D + col) = __floats2half2_rn(v2, v3);
        }
    }
#pragma unroll
    for (int mt = 0; mt < 2; mt++)
#pragma unroll
        for (int hf = 0; hf < 2; hf++) {
            float s = sp[mt][hf], d = dp[mt][hf];
            s += __shfl_xor_sync(0xffffffffu, s, 1);
            s += __shfl_xor_sync(0xffffffffu, s, 2);
            d += __shfl_xor_sync(0xffffffffu, d, 1);
            d += __shfl_xor_sync(0xffffffffu, d, 2);
            if (qk == 0) {
                int rl = warpM * 32 + mt * 16 + groupr + hf * 8;
                atomicAdd(&ssrc[rl], s);
                atomicAdd(&sdst[rl], d);
            }
        }
    __syncthreads();
    if (tid < GBM) {
        int m = m0 + tid;
        if (m < NN) {
            atomicAdd(&srcp[m], ssrc[tid]);
            atomicAdd(&dstp[m], sdst[tid]);
        }
    }
}

// ---------------------------------------------------------------------------
// Attention + aggregation + ELU. One warp per node; fp16 gather + fp16 out.
// ---------------------------------------------------------------------------
__global__ void agg_kernel(const void* __restrict__ neighbors, int layer) {
    int w    = (blockIdx.x * blockDim.x + threadIdx.x) >> 5;
    int lane = threadIdx.x & 31;
    if (w >= NN) return;
    const float* srcp = g_src + layer * NN;
    const float* dstp = g_dst + layer * NN;

    int   nbr = 0;
    float e   = -1e30f;
    if (lane < KNB) {
        nbr = load_idx(neighbors, (long long)w * KNB + lane);
        e   = srcp[w] + dstp[nbr];
        e   = e > 0.f ? e : NEG_SLOPE * e;
    }
    float m = e;
#pragma unroll
    for (int o = 8; o > 0; o >>= 1) m = fmaxf(m, __shfl_xor_sync(0xffffffffu, m, o));
    float ex = (lane < KNB) ? __expf(e - m) : 0.f;
    float s = ex;
#pragma unroll
    for (int o = 8; o > 0; o >>= 1) s += __shfl_xor_sync(0xffffffffu, s, o);
    float alpha = ex / s;

    float acc[8] = {0.f, 0.f, 0.f, 0.f, 0.f, 0.f, 0.f, 0.f};
#pragma unroll
    for (int k = 0; k < KNB; k++) {
        float al  = __shfl_sync(0xffffffffu, alpha, k);
        int   idx = __shfl_sync(0xffffffffu, nbr, k);
        uint4 v = *((const uint4*)(g_hw_h + (size_t)idx * D) + lane);
        const __half2* hp = (const __half2*)&v;
        float2 f0 = __half22float2(hp[0]);
        float2 f1 = __half22float2(hp[1]);
        float2 f2 = __half22float2(hp[2]);
        float2 f3 = __half22float2(hp[3]);
        acc[0] += al * f0.x; acc[1] += al * f0.y;
        acc[2] += al * f1.x; acc[3] += al * f1.y;
        acc[4] += al * f2.x; acc[5] += al * f2.y;
        acc[6] += al * f3.x; acc[7] += al * f3.y;
    }
#pragma unroll
    for (int j = 0; j < 8; j++)
        acc[j] = acc[j] > 0.f ? acc[j] : __expf(acc[j]) - 1.f;

    uint4 ov;
    __half2* op = (__half2*)&ov;
    op[0] = __floats2half2_rn(acc[0], acc[1]);
    op[1] = __floats2half2_rn(acc[2], acc[3]);
    op[2] = __floats2half2_rn(acc[4], acc[5]);
    op[3] = __floats2half2_rn(acc[6], acc[7]);
    *((uint4*)(g_h16 + (size_t)w * D) + lane) = ov;
}

// ---------------------------------------------------------------------------
// Classification head.
// ---------------------------------------------------------------------------
__global__ void cls_kernel(const void* __restrict__ node,
                           const float* __restrict__ cls_W,
                           const float* __restrict__ cls_b,
                           float* __restrict__ out) {
    int b    = (blockIdx.x * blockDim.x + threadIdx.x) >> 5;
    int lane = threadIdx.x & 31;
    if (b >= NB) return;
    int n = load_idx(node, b);
    uint4 v = *((const uint4*)(g_h16 + (size_t)n * D) + lane);
    const __half2* hp = (const __half2*)&v;
    float2 f0 = __half22float2(hp[0]);
    float2 f1 = __half22float2(hp[1]);
    float2 f2 = __half22float2(hp[2]);
    float2 f3 = __half22float2(hp[3]);
    for (int c = 0; c < NC; c++) {
        const float4* wr = (const float4*)(cls_W + (size_t)c * D);
        float4 w0 = wr[lane * 2], w1 = wr[lane * 2 + 1];
        float p = f0.x * w0.x + f0.y * w0.y + f1.x * w0.z + f1.y * w0.w
                + f2.x * w1.x + f2.y * w1.y + f3.x * w1.z + f3.y * w1.w;
        p = warp_red_sum(p);
        if (lane == 0) out[(size_t)b * NC + c] = p + cls_b[c];
    }
}

// ---------------------------------------------------------------------------
extern "C" void kernel_launch(void* const* d_in, const int* in_sizes, int n_in,
                              void* d_out, int out_size) {
    const void*  node      = d_in[0];
    const float* node_feat = (const float*)d_in[1];
    const void*  neighbors = d_in[2];
    const float* Ws        = (const float*)d_in[3];
    const float* a_src     = (const float*)d_in[4];
    const float* a_dst     = (const float*)d_in[5];
    const float* cls_W     = (const float*)d_in[6];
    const float* cls_b     = (const float*)d_in[7];
    float* out = (float*)d_out;

    const int warp_blocks = (NN * 32 + 255) / 256;  // 6250

    int n_words = in_sizes[2] < 2048 ? in_sizes[2] : 2048;
    init_kernel<<<(2 * NN + 255) / 256, 256>>>(Ws, (const int*)neighbors, n_words);

    dim3 ggrid(D / GBN, (NN + GBM - 1) / GBM);      // (2, 391)
    gemm0_kernel<<<ggrid, 256>>>(node_feat, a_src, a_dst);
    agg_kernel<<<warp_blocks, 256>>>(neighbors, 0);
    gemm1_kernel<<<ggrid, 512>>>(a_src + D, a_dst + D);
    agg_kernel<<<warp_blocks, 256>>>(neighbors, 1);
    cls_kernel<<<(NB * 32 + 255) / 256, 256>>>(node, cls_W, cls_b, out);
}